// round 5
// baseline (speedup 1.0000x reference)
#include <cuda_runtime.h>
#include <cuda_fp16.h>
#include <math.h>
#include <stdint.h>

#define NN 100000
#define NE 1600000
#define NF 256
#define NH 128
#define NC 41
#define GS 48   // padded gs row (halfs)

#define SCAN_TILE 1024
#define NSB ((NN + SCAN_TILE - 1) / SCAN_TILE)

// ---------------- device scratch (static; no allocations allowed) ----------
__device__ float  g_deg[NN];
__device__ float  g_dinv[NN];
__device__ int    g_cnt[NN];
__device__ int    g_rowptr[NN + 1];
__device__ int    g_cursor[NN];
__device__ int    g_bsum[NSB];
__device__ int    g_boff[NSB];
__device__ int    g_csrc[NE];
__device__ float  g_cw[NE];
__device__ __half g_hsh[NN * NH];   // fp16: dinv * (x @ W1)
__device__ float  g_hr[NN * NH];    // fp32: relu(layer1 out)
__device__ __half g_gsh[NN * GS];   // fp16: dinv * (hr @ W2), padded to 48

// ---------------- packed f32x2 helpers --------------------------------------
__device__ __forceinline__ unsigned long long pk2(float lo, float hi) {
    unsigned long long r;
    asm("mov.b64 %0, {%1, %2};" : "=l"(r) : "f"(lo), "f"(hi));
    return r;
}
__device__ __forceinline__ void upk2(unsigned long long v, float& lo, float& hi) {
    asm("mov.b64 {%0, %1}, %2;" : "=f"(lo), "=f"(hi) : "l"(v));
}
__device__ __forceinline__ void ffma2(unsigned long long& d,
                                      unsigned long long a,
                                      unsigned long long b) {
    asm("fma.rn.f32x2 %0, %1, %2, %0;" : "+l"(d) : "l"(a), "l"(b));
}

// ---------------- degree / histogram ---------------------------------------
__global__ void k_init() {
    int i = blockIdx.x * blockDim.x + threadIdx.x;
    if (i < NN) { g_deg[i] = 1.0f; g_cnt[i] = 0; }   // self-loop weight 1
}

__global__ void k_hist(const int* __restrict__ ei, const float* __restrict__ ew) {
    int e = blockIdx.x * blockDim.x + threadIdx.x;
    if (e < NE) {
        int dst = ei[NE + e];
        atomicAdd(&g_deg[dst], ew[e]);
        atomicAdd(&g_cnt[dst], 1);
    }
}

__global__ void k_dinv() {
    int i = blockIdx.x * blockDim.x + threadIdx.x;
    if (i < NN) {
        float d = g_deg[i];
        g_dinv[i] = (d > 0.0f) ? rsqrtf(d) : 0.0f;
    }
}

// ---------------- 3-pass exclusive scan of g_cnt -> g_rowptr ---------------
__global__ void k_scan1() {
    __shared__ int sh[256];
    int b = blockIdx.x, t = threadIdx.x;
    int base = b * SCAN_TILE + t * 4;
    int s = 0;
#pragma unroll
    for (int j = 0; j < 4; j++) {
        int idx = base + j;
        if (idx < NN) s += g_cnt[idx];
    }
    sh[t] = s; __syncthreads();
    for (int off = 128; off > 0; off >>= 1) {
        if (t < off) sh[t] += sh[t + off];
        __syncthreads();
    }
    if (t == 0) g_bsum[b] = sh[0];
}

__global__ void k_scan2() {
    __shared__ int sh[NSB];
    int t = threadIdx.x;
    if (t < NSB) sh[t] = g_bsum[t];
    __syncthreads();
    if (t == 0) {
        int run = 0;
        for (int b = 0; b < NSB; b++) { int v = sh[b]; sh[b] = run; run += v; }
    }
    __syncthreads();
    if (t < NSB) g_boff[t] = sh[t];
}

__global__ void k_scan3() {
    __shared__ int sh[256];
    int b = blockIdx.x, t = threadIdx.x;
    int base = b * SCAN_TILE + t * 4;
    int v[4]; int s = 0;
#pragma unroll
    for (int j = 0; j < 4; j++) {
        int idx = base + j;
        v[j] = (idx < NN) ? g_cnt[idx] : 0;
        s += v[j];
    }
    sh[t] = s; __syncthreads();
    for (int off = 1; off < 256; off <<= 1) {
        int add = (t >= off) ? sh[t - off] : 0;
        __syncthreads();
        sh[t] += add;
        __syncthreads();
    }
    int excl = ((t > 0) ? sh[t - 1] : 0) + g_boff[b];
#pragma unroll
    for (int j = 0; j < 4; j++) {
        int idx = base + j;
        if (idx < NN) { g_rowptr[idx] = excl; g_cursor[idx] = excl; }
        excl += v[j];
    }
    if (b == 0 && t == 0) g_rowptr[NN] = NE;
}

__global__ void k_csr(const int* __restrict__ ei, const float* __restrict__ ew) {
    int e = blockIdx.x * blockDim.x + threadIdx.x;
    if (e < NE) {
        int src = ei[e];
        int dst = ei[NE + e];
        int pos = atomicAdd(&g_cursor[dst], 1);
        g_csrc[pos] = src;
        g_cw[pos]   = ew[e];
    }
}

// ---------------- packed-f32x2 tiled GEMM, fp16 output ----------------------
// B held in smem PRE-DUPLICATED as {v,v} f32x2 pairs -> no packing MOVs in loop
// WHICH==0: A = x (ext),  C = g_hsh  (K=NF, NOUT=NH,  OSTR=NH)
// WHICH==1: A = g_hr,     C = g_gsh  (K=NH, NOUT=NC,  OSTR=GS, pad cols -> 0)
template<int BM, int BN, int BK, int TM, int TN, int K, int NOUT, int OSTR, int WHICH>
__global__ void k_gemm_p(const float* __restrict__ Aext, const float* __restrict__ B) {
    const int NT = (BM / TM) * (BN / TN);
    __shared__ float As[BK][BM + 4];                 // +4: 16B-aligned rows
    __shared__ unsigned long long Bs2[BK][BN];       // duplicated pairs
    const float*  A = (WHICH == 0) ? Aext : g_hr;
    __half*       C = (WHICH == 0) ? g_hsh : g_gsh;

    int tid  = threadIdx.x;
    int row0 = blockIdx.x * BM;
    int trow = tid / (BN / TN);
    int tcol = tid % (BN / TN);

    unsigned long long acc[TM / 2][TN];
#pragma unroll
    for (int i = 0; i < TM / 2; i++)
#pragma unroll
        for (int j = 0; j < TN; j++) acc[i][j] = 0ull;

    for (int kt = 0; kt < K; kt += BK) {
#pragma unroll 4
        for (int i = tid; i < BM * BK; i += NT) {
            int m = i / BK, k = i % BK;
            int gm = row0 + m;
            As[k][m] = (gm < NN) ? A[gm * K + kt + k] : 0.0f;
        }
#pragma unroll 4
        for (int i = tid; i < BK * BN; i += NT) {
            int k = i / BN, n = i % BN;
            float v = (n < NOUT) ? B[(kt + k) * NOUT + n] : 0.0f;
            Bs2[k][n] = pk2(v, v);
        }
        __syncthreads();
#pragma unroll
        for (int kk = 0; kk < BK; kk++) {
            // A: TM floats as TM/4 x LDS.128 (warp-uniform broadcast address)
            unsigned long long ra[TM / 2];
            const float4* ap4 = reinterpret_cast<const float4*>(&As[kk][trow * TM]);
#pragma unroll
            for (int i = 0; i < TM / 4; i++) {
                float4 q = ap4[i];
                ra[2 * i]     = pk2(q.x, q.y);
                ra[2 * i + 1] = pk2(q.z, q.w);
            }
            // B: TN duplicated pairs via TN/2 LDS.128
            unsigned long long rb[TN];
            const ulonglong2* bp = reinterpret_cast<const ulonglong2*>(&Bs2[kk][tcol * TN]);
#pragma unroll
            for (int j = 0; j < TN / 2; j++) {
                ulonglong2 q = bp[j];
                rb[2 * j]     = q.x;
                rb[2 * j + 1] = q.y;
            }
#pragma unroll
            for (int i = 0; i < TM / 2; i++)
#pragma unroll
                for (int j = 0; j < TN; j++)
                    ffma2(acc[i][j], ra[i], rb[j]);
        }
        __syncthreads();
    }

    // epilogue: scale by dinv, convert to fp16, 8B stores
    int nb = tcol * TN;
    bool nok = (nb < OSTR);   // for WHICH==1, skip n in [48,64)
#pragma unroll
    for (int i = 0; i < TM / 2; i++) {
        int m0 = row0 + trow * TM + 2 * i;
        int m1 = m0 + 1;
        float r0[TN], r1[TN];
#pragma unroll
        for (int j = 0; j < TN; j++) upk2(acc[i][j], r0[j], r1[j]);
        if (nok && m0 < NN) {
            float dv = g_dinv[m0];
            __half2 h0 = __floats2half2_rn(dv * r0[0], dv * r0[1]);
            __half2 h1 = __floats2half2_rn(dv * r0[2], dv * r0[3]);
            uint2 pkd = make_uint2(*reinterpret_cast<uint32_t*>(&h0),
                                   *reinterpret_cast<uint32_t*>(&h1));
            *reinterpret_cast<uint2*>(&C[(size_t)m0 * OSTR + nb]) = pkd;
        }
        if (nok && m1 < NN) {
            float dv = g_dinv[m1];
            __half2 h0 = __floats2half2_rn(dv * r1[0], dv * r1[1]);
            __half2 h1 = __floats2half2_rn(dv * r1[2], dv * r1[3]);
            uint2 pkd = make_uint2(*reinterpret_cast<uint32_t*>(&h0),
                                   *reinterpret_cast<uint32_t*>(&h1));
            *reinterpret_cast<uint2*>(&C[(size_t)m1 * OSTR + nb]) = pkd;
        }
    }
}

// ---------------- pull aggregation layer 1 (warp/node, 4x unrolled) --------
__global__ void k_pull1(const float* __restrict__ b1) {
    int gw   = (blockIdx.x * blockDim.x + threadIdx.x) >> 5;
    int lane = threadIdx.x & 31;
    if (gw >= NN) return;

    int rs = g_rowptr[gw], re = g_rowptr[gw + 1];
    float4 accA = make_float4(0.f, 0.f, 0.f, 0.f);
    float4 accB = make_float4(0.f, 0.f, 0.f, 0.f);

    for (int base = rs; base < re; base += 32) {
        int cnt = re - base; if (cnt > 32) cnt = 32;
        int s = 0; float wv = 0.0f;
        if (lane < cnt) { s = g_csrc[base + lane]; wv = g_cw[base + lane]; }
        int j = 0;
        for (; j + 4 <= cnt; j += 4) {
            int   s0 = __shfl_sync(0xffffffffu, s,  j);
            int   s1 = __shfl_sync(0xffffffffu, s,  j + 1);
            int   s2 = __shfl_sync(0xffffffffu, s,  j + 2);
            int   s3 = __shfl_sync(0xffffffffu, s,  j + 3);
            float w0 = __shfl_sync(0xffffffffu, wv, j);
            float w1 = __shfl_sync(0xffffffffu, wv, j + 1);
            float w2 = __shfl_sync(0xffffffffu, wv, j + 2);
            float w3 = __shfl_sync(0xffffffffu, wv, j + 3);
            uint2 p0 = *reinterpret_cast<const uint2*>(&g_hsh[(size_t)s0 * NH + lane * 4]);
            uint2 p1 = *reinterpret_cast<const uint2*>(&g_hsh[(size_t)s1 * NH + lane * 4]);
            uint2 p2 = *reinterpret_cast<const uint2*>(&g_hsh[(size_t)s2 * NH + lane * 4]);
            uint2 p3 = *reinterpret_cast<const uint2*>(&g_hsh[(size_t)s3 * NH + lane * 4]);
            float2 a0 = __half22float2(*reinterpret_cast<__half2*>(&p0.x));
            float2 b0 = __half22float2(*reinterpret_cast<__half2*>(&p0.y));
            float2 a1 = __half22float2(*reinterpret_cast<__half2*>(&p1.x));
            float2 b1v = __half22float2(*reinterpret_cast<__half2*>(&p1.y));
            float2 a2 = __half22float2(*reinterpret_cast<__half2*>(&p2.x));
            float2 b2v = __half22float2(*reinterpret_cast<__half2*>(&p2.y));
            float2 a3 = __half22float2(*reinterpret_cast<__half2*>(&p3.x));
            float2 b3v = __half22float2(*reinterpret_cast<__half2*>(&p3.y));
            accA.x += w0 * a0.x; accA.y += w0 * a0.y; accA.z += w0 * b0.x;  accA.w += w0 * b0.y;
            accB.x += w1 * a1.x; accB.y += w1 * a1.y; accB.z += w1 * b1v.x; accB.w += w1 * b1v.y;
            accA.x += w2 * a2.x; accA.y += w2 * a2.y; accA.z += w2 * b2v.x; accA.w += w2 * b2v.y;
            accB.x += w3 * a3.x; accB.y += w3 * a3.y; accB.z += w3 * b3v.x; accB.w += w3 * b3v.y;
        }
        for (; j < cnt; j++) {
            int   sj = __shfl_sync(0xffffffffu, s,  j);
            float wj = __shfl_sync(0xffffffffu, wv, j);
            uint2 p = *reinterpret_cast<const uint2*>(&g_hsh[(size_t)sj * NH + lane * 4]);
            float2 fa = __half22float2(*reinterpret_cast<__half2*>(&p.x));
            float2 fb = __half22float2(*reinterpret_cast<__half2*>(&p.y));
            accA.x += wj * fa.x; accA.y += wj * fa.y;
            accA.z += wj * fb.x; accA.w += wj * fb.y;
        }
    }

    float4 acc = make_float4(accA.x + accB.x, accA.y + accB.y,
                             accA.z + accB.z, accA.w + accB.w);
    float dv = g_dinv[gw];
    uint2 sp = *reinterpret_cast<const uint2*>(&g_hsh[(size_t)gw * NH + lane * 4]);
    float2 sa = __half22float2(*reinterpret_cast<__half2*>(&sp.x));
    float2 sb = __half22float2(*reinterpret_cast<__half2*>(&sp.y));
    float4 bb = *reinterpret_cast<const float4*>(&b1[lane * 4]);
    float4 r;
    r.x = fmaxf(dv * (acc.x + sa.x) + bb.x, 0.0f);
    r.y = fmaxf(dv * (acc.y + sa.y) + bb.y, 0.0f);
    r.z = fmaxf(dv * (acc.z + sb.x) + bb.z, 0.0f);
    r.w = fmaxf(dv * (acc.w + sb.y) + bb.w, 0.0f);
    *reinterpret_cast<float4*>(&g_hr[(size_t)gw * NH + lane * 4]) = r;
}

// ---------------- pull layer 2 + bias + log_softmax (4x unrolled) ----------
__global__ void k_pull2(const float* __restrict__ b2, float* __restrict__ out) {
    int gw   = (blockIdx.x * blockDim.x + threadIdx.x) >> 5;
    int lane = threadIdx.x & 31;
    if (gw >= NN) return;

    int rs = g_rowptr[gw], re = g_rowptr[gw + 1];
    bool act = (lane < GS / 2);
    size_t lo = 2 * lane;
    float2 accA = make_float2(0.f, 0.f);
    float2 accB = make_float2(0.f, 0.f);

    for (int base = rs; base < re; base += 32) {
        int cnt = re - base; if (cnt > 32) cnt = 32;
        int s = 0; float wv = 0.0f;
        if (lane < cnt) { s = g_csrc[base + lane]; wv = g_cw[base + lane]; }
        int j = 0;
        for (; j + 4 <= cnt; j += 4) {
            int   s0 = __shfl_sync(0xffffffffu, s,  j);
            int   s1 = __shfl_sync(0xffffffffu, s,  j + 1);
            int   s2 = __shfl_sync(0xffffffffu, s,  j + 2);
            int   s3 = __shfl_sync(0xffffffffu, s,  j + 3);
            float w0 = __shfl_sync(0xffffffffu, wv, j);
            float w1 = __shfl_sync(0xffffffffu, wv, j + 1);
            float w2 = __shfl_sync(0xffffffffu, wv, j + 2);
            float w3 = __shfl_sync(0xffffffffu, wv, j + 3);
            if (act) {
                uint32_t p0 = *reinterpret_cast<const uint32_t*>(&g_gsh[(size_t)s0 * GS + lo]);
                uint32_t p1 = *reinterpret_cast<const uint32_t*>(&g_gsh[(size_t)s1 * GS + lo]);
                uint32_t p2 = *reinterpret_cast<const uint32_t*>(&g_gsh[(size_t)s2 * GS + lo]);
                uint32_t p3 = *reinterpret_cast<const uint32_t*>(&g_gsh[(size_t)s3 * GS + lo]);
                float2 f0 = __half22float2(*reinterpret_cast<__half2*>(&p0));
                float2 f1 = __half22float2(*reinterpret_cast<__half2*>(&p1));
                float2 f2 = __half22float2(*reinterpret_cast<__half2*>(&p2));
                float2 f3 = __half22float2(*reinterpret_cast<__half2*>(&p3));
                accA.x += w0 * f0.x; accA.y += w0 * f0.y;
                accB.x += w1 * f1.x; accB.y += w1 * f1.y;
                accA.x += w2 * f2.x; accA.y += w2 * f2.y;
                accB.x += w3 * f3.x; accB.y += w3 * f3.y;
            }
        }
        for (; j < cnt; j++) {
            int   sj = __shfl_sync(0xffffffffu, s,  j);
            float wj = __shfl_sync(0xffffffffu, wv, j);
            if (act) {
                uint32_t p = *reinterpret_cast<const uint32_t*>(&g_gsh[(size_t)sj * GS + lo]);
                float2 f = __half22float2(*reinterpret_cast<__half2*>(&p));
                accA.x += wj * f.x; accA.y += wj * f.y;
            }
        }
    }

    float2 acc = make_float2(accA.x + accB.x, accA.y + accB.y);
    float dv = g_dinv[gw];
    int f0 = 2 * lane, f1 = 2 * lane + 1;
    float v0 = -1e30f, v1 = -1e30f;
    if (act) {
        uint32_t sp = *reinterpret_cast<const uint32_t*>(&g_gsh[(size_t)gw * GS + lo]);
        float2 sf = __half22float2(*reinterpret_cast<__half2*>(&sp));
        if (f0 < NC) v0 = dv * (acc.x + sf.x) + b2[f0];
        if (f1 < NC) v1 = dv * (acc.y + sf.y) + b2[f1];
    }

    float m = fmaxf(v0, v1);
#pragma unroll
    for (int off = 16; off > 0; off >>= 1)
        m = fmaxf(m, __shfl_xor_sync(0xffffffffu, m, off));

    float s = ((f0 < NC && act) ? expf(v0 - m) : 0.0f)
            + ((f1 < NC && act) ? expf(v1 - m) : 0.0f);
#pragma unroll
    for (int off = 16; off > 0; off >>= 1)
        s += __shfl_xor_sync(0xffffffffu, s, off);

    float lse = logf(s) + m;
    if (act && f0 < NC) out[(size_t)gw * NC + f0] = v0 - lse;
    if (act && f1 < NC) out[(size_t)gw * NC + f1] = v1 - lse;
}

// ---------------- launch ---------------------------------------------------
extern "C" void kernel_launch(void* const* d_in, const int* in_sizes, int n_in,
                              void* d_out, int out_size) {
    const float* x  = (const float*)d_in[0];
    const int*   ei = (const int*)  d_in[1];
    const float* ew = (const float*)d_in[2];
    const float* W1 = (const float*)d_in[3];
    const float* b1 = (const float*)d_in[4];
    const float* W2 = (const float*)d_in[5];
    const float* b2 = (const float*)d_in[6];
    float* out = (float*)d_out;

    k_init<<<(NN + 255) / 256, 256>>>();
    k_hist<<<(NE + 255) / 256, 256>>>(ei, ew);
    k_dinv<<<(NN + 255) / 256, 256>>>();
    k_scan1<<<NSB, 256>>>();
    k_scan2<<<1, 128>>>();
    k_scan3<<<NSB, 256>>>();
    k_csr<<<(NE + 255) / 256, 256>>>(ei, ew);

    // layer 1: hsh = fp16(dinv * (x @ W1)) — f32x2 packed, 256 threads
    k_gemm_p<128, 128, 16, 16, 4, NF, NH, NH, 0><<<(NN + 127) / 128, 256>>>(x, W1);
    k_pull1<<<(NN * 32 + 255) / 256, 256>>>(b1);

    // layer 2: gsh = fp16(dinv * (hr @ W2)) — f32x2 packed, 128 threads
    k_gemm_p<128, 64, 16, 16, 4, NH, NC, GS, 1><<<(NN + 127) / 128, 128>>>(nullptr, W2);
    k_pull2<<<(NN * 32 + 255) / 256, 256>>>(b2, out);
}

// round 6
// speedup vs baseline: 1.2464x; 1.2464x over previous
#include <cuda_runtime.h>
#include <cuda_fp16.h>
#include <math.h>
#include <stdint.h>

#define NN 100000
#define NE 1600000
#define NF 256
#define NH 128
#define NC 41
#define GS 48   // padded gs row (halfs)

#define SCAN_TILE 1024
#define NSB ((NN + SCAN_TILE - 1) / SCAN_TILE)

// ---------------- device scratch (static; no allocations allowed) ----------
__device__ float  g_deg[NN];
__device__ float  g_dinv[NN];
__device__ int    g_cnt[NN];
__device__ int    g_rowptr[NN + 1];
__device__ int    g_cursor[NN];
__device__ int    g_bsum[NSB];
__device__ int    g_boff[NSB];
__device__ int    g_csrc[NE];
__device__ float  g_cw[NE];
__device__ __half g_hsh[NN * NH];   // fp16: dinv * (x @ W1)
__device__ float  g_hr[NN * NH];    // fp32: relu(layer1 out)
__device__ __half g_gsh[NN * GS];   // fp16: dinv * (hr @ W2), padded to 48

// ---------------- packed f32x2 helpers --------------------------------------
__device__ __forceinline__ unsigned long long pk2(float lo, float hi) {
    unsigned long long r;
    asm("mov.b64 %0, {%1, %2};" : "=l"(r) : "f"(lo), "f"(hi));
    return r;
}
__device__ __forceinline__ void upk2(unsigned long long v, float& lo, float& hi) {
    asm("mov.b64 {%0, %1}, %2;" : "=f"(lo), "=f"(hi) : "l"(v));
}
__device__ __forceinline__ void ffma2(unsigned long long& d,
                                      unsigned long long a,
                                      unsigned long long b) {
    asm("fma.rn.f32x2 %0, %1, %2, %0;" : "+l"(d) : "l"(a), "l"(b));
}

// ---------------- degree / histogram ---------------------------------------
__global__ void k_init() {
    int i = blockIdx.x * blockDim.x + threadIdx.x;
    if (i < NN) { g_deg[i] = 1.0f; g_cnt[i] = 0; }   // self-loop weight 1
}

__global__ void k_hist(const int* __restrict__ ei, const float* __restrict__ ew) {
    int e = blockIdx.x * blockDim.x + threadIdx.x;
    if (e < NE) {
        int dst = ei[NE + e];
        atomicAdd(&g_deg[dst], ew[e]);
        atomicAdd(&g_cnt[dst], 1);
    }
}

__global__ void k_dinv() {
    int i = blockIdx.x * blockDim.x + threadIdx.x;
    if (i < NN) {
        float d = g_deg[i];
        g_dinv[i] = (d > 0.0f) ? rsqrtf(d) : 0.0f;
    }
}

// ---------------- 3-pass exclusive scan of g_cnt -> g_rowptr ---------------
__global__ void k_scan1() {
    __shared__ int sh[256];
    int b = blockIdx.x, t = threadIdx.x;
    int base = b * SCAN_TILE + t * 4;
    int s = 0;
#pragma unroll
    for (int j = 0; j < 4; j++) {
        int idx = base + j;
        if (idx < NN) s += g_cnt[idx];
    }
    sh[t] = s; __syncthreads();
    for (int off = 128; off > 0; off >>= 1) {
        if (t < off) sh[t] += sh[t + off];
        __syncthreads();
    }
    if (t == 0) g_bsum[b] = sh[0];
}

__global__ void k_scan2() {
    __shared__ int sh[NSB];
    int t = threadIdx.x;
    if (t < NSB) sh[t] = g_bsum[t];
    __syncthreads();
    if (t == 0) {
        int run = 0;
        for (int b = 0; b < NSB; b++) { int v = sh[b]; sh[b] = run; run += v; }
    }
    __syncthreads();
    if (t < NSB) g_boff[t] = sh[t];
}

__global__ void k_scan3() {
    __shared__ int sh[256];
    int b = blockIdx.x, t = threadIdx.x;
    int base = b * SCAN_TILE + t * 4;
    int v[4]; int s = 0;
#pragma unroll
    for (int j = 0; j < 4; j++) {
        int idx = base + j;
        v[j] = (idx < NN) ? g_cnt[idx] : 0;
        s += v[j];
    }
    sh[t] = s; __syncthreads();
    for (int off = 1; off < 256; off <<= 1) {
        int add = (t >= off) ? sh[t - off] : 0;
        __syncthreads();
        sh[t] += add;
        __syncthreads();
    }
    int excl = ((t > 0) ? sh[t - 1] : 0) + g_boff[b];
#pragma unroll
    for (int j = 0; j < 4; j++) {
        int idx = base + j;
        if (idx < NN) { g_rowptr[idx] = excl; g_cursor[idx] = excl; }
        excl += v[j];
    }
    if (b == 0 && t == 0) g_rowptr[NN] = NE;
}

__global__ void k_csr(const int* __restrict__ ei, const float* __restrict__ ew) {
    int e = blockIdx.x * blockDim.x + threadIdx.x;
    if (e < NE) {
        int src = ei[e];
        int dst = ei[NE + e];
        int pos = atomicAdd(&g_cursor[dst], 1);
        g_csrc[pos] = src;
        g_cw[pos]   = ew[e];
    }
}

// ---------------- packed-f32x2 tiled GEMM, fp16 output ----------------------
// Round-3 inner loop (measured best) + vectorized LDG.128 global fills.
// WHICH==0: A = x (ext),  C = g_hsh  (K=NF, NOUT=NH,  OSTR=NH)
// WHICH==1: A = g_hr,     C = g_gsh  (K=NH, NOUT=NC,  OSTR=GS, pad cols -> 0)
template<int BM, int BN, int BK, int TM, int TN, int K, int NOUT, int OSTR, int WHICH>
__global__ void k_gemm_p(const float* __restrict__ Aext, const float* __restrict__ B) {
    const int NT = (BM / TM) * (BN / TN);
    __shared__ float As[BK][BM + 4];   // +4: 16B-aligned rows for LDS.128
    __shared__ float Bs[BK][BN];
    const float*  A = (WHICH == 0) ? Aext : g_hr;
    __half*       C = (WHICH == 0) ? g_hsh : g_gsh;

    int tid  = threadIdx.x;
    int row0 = blockIdx.x * BM;
    int trow = tid / (BN / TN);
    int tcol = tid % (BN / TN);

    unsigned long long acc[TM / 2][TN];
#pragma unroll
    for (int i = 0; i < TM / 2; i++)
#pragma unroll
        for (int j = 0; j < TN; j++) acc[i][j] = 0ull;

    for (int kt = 0; kt < K; kt += BK) {
        // A fill: LDG.128 (4 consecutive k), transposed 4x STS.32
#pragma unroll
        for (int i = tid; i < BM * (BK / 4); i += NT) {
            int m  = i / (BK / 4);
            int kq = i % (BK / 4);
            int gm = row0 + m;
            float4 v = make_float4(0.f, 0.f, 0.f, 0.f);
            if (gm < NN)
                v = *reinterpret_cast<const float4*>(&A[(size_t)gm * K + kt + 4 * kq]);
            As[4 * kq + 0][m] = v.x;
            As[4 * kq + 1][m] = v.y;
            As[4 * kq + 2][m] = v.z;
            As[4 * kq + 3][m] = v.w;
        }
        // B fill
        if (WHICH == 0) {
            // NOUT == BN == 128: vector load + STS.128
#pragma unroll
            for (int i = tid; i < BK * (BN / 4); i += NT) {
                int k  = i / (BN / 4);
                int nq = i % (BN / 4);
                float4 v = *reinterpret_cast<const float4*>(&B[(size_t)(kt + k) * NOUT + 4 * nq]);
                *reinterpret_cast<float4*>(&Bs[k][4 * nq]) = v;
            }
        } else {
#pragma unroll 4
            for (int i = tid; i < BK * BN; i += NT) {
                int k = i / BN, n = i % BN;
                Bs[k][n] = (n < NOUT) ? B[(size_t)(kt + k) * NOUT + n] : 0.0f;
            }
        }
        __syncthreads();
#pragma unroll
        for (int kk = 0; kk < BK; kk++) {
            // A: TM floats as TM/4 x LDS.128 (warp-uniform broadcast address)
            unsigned long long ra[TM / 2];
            const float4* ap4 = reinterpret_cast<const float4*>(&As[kk][trow * TM]);
#pragma unroll
            for (int i = 0; i < TM / 4; i++) {
                float4 q = ap4[i];
                ra[2 * i]     = pk2(q.x, q.y);
                ra[2 * i + 1] = pk2(q.z, q.w);
            }
            // B: one float4 load, broadcast-packed
            float4 bv = *reinterpret_cast<const float4*>(&Bs[kk][tcol * TN]);
            unsigned long long rb[TN];
            rb[0] = pk2(bv.x, bv.x);
            rb[1] = pk2(bv.y, bv.y);
            rb[2] = pk2(bv.z, bv.z);
            rb[3] = pk2(bv.w, bv.w);
#pragma unroll
            for (int i = 0; i < TM / 2; i++)
#pragma unroll
                for (int j = 0; j < TN; j++)
                    ffma2(acc[i][j], ra[i], rb[j]);
        }
        __syncthreads();
    }

    // epilogue: scale by dinv, convert to fp16, 8B stores
    int nb = tcol * TN;
    bool nok = (nb < OSTR);   // for WHICH==1, skip n in [48,64)
#pragma unroll
    for (int i = 0; i < TM / 2; i++) {
        int m0 = row0 + trow * TM + 2 * i;
        int m1 = m0 + 1;
        float r0[TN], r1[TN];
#pragma unroll
        for (int j = 0; j < TN; j++) upk2(acc[i][j], r0[j], r1[j]);
        if (nok && m0 < NN) {
            float dv = g_dinv[m0];
            __half2 h0 = __floats2half2_rn(dv * r0[0], dv * r0[1]);
            __half2 h1 = __floats2half2_rn(dv * r0[2], dv * r0[3]);
            uint2 pkd = make_uint2(*reinterpret_cast<uint32_t*>(&h0),
                                   *reinterpret_cast<uint32_t*>(&h1));
            *reinterpret_cast<uint2*>(&C[(size_t)m0 * OSTR + nb]) = pkd;
        }
        if (nok && m1 < NN) {
            float dv = g_dinv[m1];
            __half2 h0 = __floats2half2_rn(dv * r1[0], dv * r1[1]);
            __half2 h1 = __floats2half2_rn(dv * r1[2], dv * r1[3]);
            uint2 pkd = make_uint2(*reinterpret_cast<uint32_t*>(&h0),
                                   *reinterpret_cast<uint32_t*>(&h1));
            *reinterpret_cast<uint2*>(&C[(size_t)m1 * OSTR + nb]) = pkd;
        }
    }
}

// ---------------- pull aggregation layer 1 (warp per node, fp16 gather) ----
__global__ void k_pull1(const float* __restrict__ b1) {
    int gw   = (blockIdx.x * blockDim.x + threadIdx.x) >> 5;
    int lane = threadIdx.x & 31;
    if (gw >= NN) return;

    int rs = g_rowptr[gw], re = g_rowptr[gw + 1];
    float4 acc = make_float4(0.f, 0.f, 0.f, 0.f);

    for (int base = rs; base < re; base += 32) {
        int cnt = re - base; if (cnt > 32) cnt = 32;
        int s = 0; float wv = 0.0f;
        if (lane < cnt) { s = g_csrc[base + lane]; wv = g_cw[base + lane]; }
        for (int j = 0; j < cnt; j++) {
            int   sj = __shfl_sync(0xffffffffu, s,  j);
            float wj = __shfl_sync(0xffffffffu, wv, j);
            uint2 p = *reinterpret_cast<const uint2*>(&g_hsh[(size_t)sj * NH + lane * 4]);
            float2 fa = __half22float2(*reinterpret_cast<__half2*>(&p.x));
            float2 fb = __half22float2(*reinterpret_cast<__half2*>(&p.y));
            acc.x += wj * fa.x; acc.y += wj * fa.y;
            acc.z += wj * fb.x; acc.w += wj * fb.y;
        }
    }

    float dv = g_dinv[gw];
    uint2 sp = *reinterpret_cast<const uint2*>(&g_hsh[(size_t)gw * NH + lane * 4]);
    float2 sa = __half22float2(*reinterpret_cast<__half2*>(&sp.x));
    float2 sb = __half22float2(*reinterpret_cast<__half2*>(&sp.y));
    float4 bb = *reinterpret_cast<const float4*>(&b1[lane * 4]);
    float4 r;
    r.x = fmaxf(dv * (acc.x + sa.x) + bb.x, 0.0f);
    r.y = fmaxf(dv * (acc.y + sa.y) + bb.y, 0.0f);
    r.z = fmaxf(dv * (acc.z + sb.x) + bb.z, 0.0f);
    r.w = fmaxf(dv * (acc.w + sb.y) + bb.w, 0.0f);
    *reinterpret_cast<float4*>(&g_hr[(size_t)gw * NH + lane * 4]) = r;
}

// ---------------- pull layer 2 + bias + log_softmax (fp16 gather) ----------
// lane l (0..23) covers feats {2l, 2l+1} of the 48-padded gs rows.
__global__ void k_pull2(const float* __restrict__ b2, float* __restrict__ out) {
    int gw   = (blockIdx.x * blockDim.x + threadIdx.x) >> 5;
    int lane = threadIdx.x & 31;
    if (gw >= NN) return;

    int rs = g_rowptr[gw], re = g_rowptr[gw + 1];
    bool act = (lane < GS / 2);
    float2 acc = make_float2(0.f, 0.f);

    for (int base = rs; base < re; base += 32) {
        int cnt = re - base; if (cnt > 32) cnt = 32;
        int s = 0; float wv = 0.0f;
        if (lane < cnt) { s = g_csrc[base + lane]; wv = g_cw[base + lane]; }
        for (int j = 0; j < cnt; j++) {
            int   sj = __shfl_sync(0xffffffffu, s,  j);
            float wj = __shfl_sync(0xffffffffu, wv, j);
            if (act) {
                uint32_t p = *reinterpret_cast<const uint32_t*>(
                    &g_gsh[(size_t)sj * GS + 2 * lane]);
                float2 f = __half22float2(*reinterpret_cast<__half2*>(&p));
                acc.x += wj * f.x; acc.y += wj * f.y;
            }
        }
    }

    float dv = g_dinv[gw];
    int f0 = 2 * lane, f1 = 2 * lane + 1;
    float v0 = -1e30f, v1 = -1e30f;
    if (act) {
        uint32_t sp = *reinterpret_cast<const uint32_t*>(
            &g_gsh[(size_t)gw * GS + 2 * lane]);
        float2 sf = __half22float2(*reinterpret_cast<__half2*>(&sp));
        if (f0 < NC) v0 = dv * (acc.x + sf.x) + b2[f0];
        if (f1 < NC) v1 = dv * (acc.y + sf.y) + b2[f1];
    }

    float m = fmaxf(v0, v1);
#pragma unroll
    for (int off = 16; off > 0; off >>= 1)
        m = fmaxf(m, __shfl_xor_sync(0xffffffffu, m, off));

    float s = ((f0 < NC && act) ? expf(v0 - m) : 0.0f)
            + ((f1 < NC && act) ? expf(v1 - m) : 0.0f);
#pragma unroll
    for (int off = 16; off > 0; off >>= 1)
        s += __shfl_xor_sync(0xffffffffu, s, off);

    float lse = logf(s) + m;
    if (act && f0 < NC) out[(size_t)gw * NC + f0] = v0 - lse;
    if (act && f1 < NC) out[(size_t)gw * NC + f1] = v1 - lse;
}

// ---------------- launch ---------------------------------------------------
// NOTE: gemm1 deliberately placed as the 4th launch — ncu's -s/-c window has
// been capturing launch #4 every round; this puts the dominant kernel in the
// profiled slot (scan1/2/3 only depend on g_cnt, so the reorder is legal).
extern "C" void kernel_launch(void* const* d_in, const int* in_sizes, int n_in,
                              void* d_out, int out_size) {
    const float* x  = (const float*)d_in[0];
    const int*   ei = (const int*)  d_in[1];
    const float* ew = (const float*)d_in[2];
    const float* W1 = (const float*)d_in[3];
    const float* b1 = (const float*)d_in[4];
    const float* W2 = (const float*)d_in[5];
    const float* b2 = (const float*)d_in[6];
    float* out = (float*)d_out;

    k_init<<<(NN + 255) / 256, 256>>>();
    k_hist<<<(NE + 255) / 256, 256>>>(ei, ew);
    k_dinv<<<(NN + 255) / 256, 256>>>();

    // layer 1 GEMM: hsh = fp16(dinv * (x @ W1))  [launch #4 -> profiled]
    k_gemm_p<128, 128, 16, 16, 4, NF, NH, NH, 0><<<(NN + 127) / 128, 256>>>(x, W1);

    k_scan1<<<NSB, 256>>>();
    k_scan2<<<1, 128>>>();
    k_scan3<<<NSB, 256>>>();
    k_csr<<<(NE + 255) / 256, 256>>>(ei, ew);

    k_pull1<<<(NN * 32 + 255) / 256, 256>>>(b1);

    // layer 2: gsh = fp16(dinv * (hr @ W2))
    k_gemm_p<128, 64, 16, 16, 4, NH, NC, GS, 1><<<(NN + 127) / 128, 128>>>(nullptr, W2);
    k_pull2<<<(NN * 32 + 255) / 256, 256>>>(b2, out);
}